// round 12
// baseline (speedup 1.0000x reference)
#include <cuda_runtime.h>
#include <cuda_fp16.h>
#include <cstdint>

// x[32,64,112,112] (*) w[128,64,3,3] + b[128] -> out[32,128,112,112], pad=1
// Conv as 9 shifted K=32 GEMM passes x 2 ic-halves. CTA = (n, oh): D[128 oc][112 px],
// 256 thr, 2 CTA/SM. fp16 mma m16n8k16 (f32 accum). One fused prep kernel:
// x -> Xt fp16 NHWC (vectorized) and w -> Wt fp16 re-laid.

#define KTOT 576
#define STRB 80                           // smem row stride (bytes): conflict-free ldsm
#define RAW_BYTES  (342*STRB)             // 27360
#define ABUF_BYTES (128*STRB)             // 10240
#define SMEM_BYTES (RAW_BYTES + 2*ABUF_BYTES)   // 47840

__device__ __align__(16) __half Wt[2*9*128*32];              // re-laid weights
__device__ __align__(16) __half Xt[(size_t)32*112*112*64];   // NHWC input

__device__ __forceinline__ void ldsm4(uint32_t* r, uint32_t addr) {
    asm volatile("ldmatrix.sync.aligned.m8n8.x4.shared.b16 {%0,%1,%2,%3}, [%4];"
                 : "=r"(r[0]), "=r"(r[1]), "=r"(r[2]), "=r"(r[3]) : "r"(addr));
}
__device__ __forceinline__ void ldsm2(uint32_t* r, uint32_t addr) {
    asm volatile("ldmatrix.sync.aligned.m8n8.x2.shared.b16 {%0,%1}, [%2];"
                 : "=r"(r[0]), "=r"(r[1]) : "r"(addr));
}
__device__ __forceinline__ void mma16(float* d, const uint32_t* a, uint32_t b0, uint32_t b1) {
    asm volatile(
        "mma.sync.aligned.m16n8k16.row.col.f32.f16.f16.f32 "
        "{%0,%1,%2,%3}, {%4,%5,%6,%7}, {%8,%9}, {%0,%1,%2,%3};"
        : "+f"(d[0]), "+f"(d[1]), "+f"(d[2]), "+f"(d[3])
        : "r"(a[0]), "r"(a[1]), "r"(a[2]), "r"(a[3]), "r"(b0), "r"(b1));
}
__device__ __forceinline__ void cpa16(uint32_t dst, const void* src) {
    asm volatile("cp.async.ca.shared.global [%0], [%1], 16;" :: "r"(dst), "l"(src));
}
__device__ __forceinline__ void cpa16z(uint32_t dst, const void* src, uint32_t sz) {
    asm volatile("cp.async.ca.shared.global [%0], [%1], 16, %2;"
                 :: "r"(dst), "l"(src), "r"(sz));
}
__device__ __forceinline__ void cpa_commit() { asm volatile("cp.async.commit_group;"); }
__device__ __forceinline__ void cpa_wait0()  { asm volatile("cp.async.wait_group 0;" ::: "memory"); }

// ---- fused prepass: blocks [0,3584) transpose x; blocks [3584,3872) re-lay w ----
__global__ __launch_bounds__(256)
void prep_all(const float* __restrict__ x, const float* __restrict__ w) {
    const int tid = threadIdx.x;
    if (blockIdx.x >= 3584) {
        const int i = (blockIdx.x - 3584) * 256 + tid;    // 73728 total
        const int icl = i & 31;
        const int t   = i >> 5;
        const int oc  = t & 127;
        const int hr  = t >> 7;
        const int r   = hr % 9;
        const int h   = hr / 9;
        Wt[i] = __float2half_rn(w[oc * KTOT + (h * 32 + icl) * 9 + r]);
        return;
    }
    __shared__ float tile[64][116];                       // stride 116: aligned STS.128
    const int n = blockIdx.x / 112, h = blockIdx.x - n * 112;
    const float* src = x + ((size_t)n * 64 * 112 + h) * 112;
    #pragma unroll
    for (int i = tid; i < 64 * 28; i += 256) {            // float4 reads, coalesced
        const int c = i / 28, w4 = i - c * 28;
        const float4 v = *reinterpret_cast<const float4*>(src + (size_t)c * 12544 + w4 * 4);
        *reinterpret_cast<float4*>(&tile[c][w4 * 4]) = v;
    }
    __syncthreads();
    __half2* dst = reinterpret_cast<__half2*>(Xt + ((size_t)(n * 112 + h) * 112) * 64);
    #pragma unroll
    for (int i = tid; i < 112 * 32; i += 256) {           // coalesced half2 writes
        const int wp = i >> 5, c2 = i & 31;
        dst[i] = __floats2half2_rn(tile[2 * c2][wp], tile[2 * c2 + 1][wp]);
    }
}

__global__ __launch_bounds__(256, 2)
void conv3x3_fp16(const float* __restrict__ bias,
                  float* __restrict__ out)
{
    extern __shared__ uint32_t sm[];

    const int tid = threadIdx.x;
    const int lid = tid & 31;
    const int wid = tid >> 5;
    const int wm  = wid & 3;                     // 32 oc per warp
    const int wn  = wid >> 2;                    // 56 px per warp

    const int bz = blockIdx.x;
    const int n  = bz / 112;
    const int oh = bz - n * 112;

    const uint32_t smem_b = (uint32_t)__cvta_generic_to_shared(sm);
    const uint32_t rawB = smem_b;                          // Raw [342 px][80B]
    const uint32_t AsmB = smem_b + RAW_BYTES;              // 2 x [128 oc][80B]

    const uint32_t aOff  = AsmB + (wm * 32 + (lid & 15)) * STRB + ((lid >> 4) << 4);
    const uint32_t bOff4 = (lid & 15) * STRB + ((lid >> 4) << 4);
    const uint32_t bOff2 = (lid & 7) * STRB + (((lid >> 3) & 1) << 4);

    float acc[2][7][4];
    #pragma unroll
    for (int mt = 0; mt < 2; ++mt)
        #pragma unroll
        for (int nt = 0; nt < 7; ++nt)
            #pragma unroll
            for (int e = 0; e < 4; ++e) acc[mt][nt][e] = 0.0f;

    // ---- A pass tile: 2x 16B cp.async from Wt ----
    auto issue_A = [&](int h, int r, int buf) {
        const __half* src = Wt + (h * 9 + r) * 4096;       // [128][32] halves
        const int q = tid & 3, ocr = tid >> 2;
        const uint32_t dbase = AsmB + buf * ABUF_BYTES;
        #pragma unroll
        for (int it = 0; it < 2; ++it) {
            const int oc = it * 64 + ocr;
            cpa16(dbase + oc * STRB + q * 16, src + oc * 32 + q * 8);
        }
    };

    // ---- raw tile for ic-half h: one 16B cp.async per (pixel, 8-ic chunk) ----
    auto issue_raw = [&](int hlf) {
        const __half* xb = Xt + (size_t)n * 12544 * 64 + hlf * 32;
        const int q = tid & 3;
        #pragma unroll 1
        for (int p = tid >> 2; p < 342; p += 64) {
            const int row = p / 114, col = p - row * 114;
            const int ih = oh - 1 + row;
            const int iw = col - 1;
            const bool ok = (ih >= 0) & (ih < 112) & (iw >= 0) & (iw < 112);
            const __half* src = ok ? xb + ((size_t)ih * 112 + iw) * 64 + q * 8 : Xt;
            cpa16z(rawB + p * STRB + q * 16, src, ok ? 16u : 0u);
        }
    };

    // ---- one (kh,kw) GEMM pass, K=32 (2 k16 mma steps) ----
    auto compute = [&](int r, int buf) {
        const int kh = r / 3, kw = r - 3 * kh;
        const uint32_t b4 = rawB + (kh * 114 + kw + wn * 56) * STRB + bOff4;
        const uint32_t b2 = rawB + (kh * 114 + kw + wn * 56 + 48) * STRB + bOff2;
        const uint32_t aB = aOff + buf * ABUF_BYTES;
        #pragma unroll
        for (int s = 0; s < 2; ++s) {
            uint32_t a0[4], a1[4];
            ldsm4(a0, aB + s * 32);
            ldsm4(a1, aB + 16 * STRB + s * 32);
            #pragma unroll
            for (int np = 0; np < 3; ++np) {
                uint32_t bf[4];
                ldsm4(bf, b4 + np * (16 * STRB) + s * 32);
                #pragma unroll
                for (int half = 0; half < 2; ++half) {
                    const int nt = np * 2 + half;
                    mma16(acc[0][nt], a0, bf[half], bf[2 + half]);
                    mma16(acc[1][nt], a1, bf[half], bf[2 + half]);
                }
            }
            uint32_t bg[2];
            ldsm2(bg, b2 + s * 32);
            mma16(acc[0][6], a0, bg[0], bg[1]);
            mma16(acc[1][6], a1, bg[0], bg[1]);
        }
    };

    // ---- pipelined main loop (R10 structure) ----
    issue_raw(0);
    issue_A(0, 0, 0);
    cpa_commit();
    cpa_wait0();
    __syncthreads();

    #pragma unroll 1
    for (int h = 0; h < 2; ++h) {
        #pragma unroll 1
        for (int r = 0; r < 9; ++r) {
            if (r < 8) { issue_A(h, r + 1, (r + 1) & 1); cpa_commit(); }
            compute(r, r & 1);
            if (r < 8) cpa_wait0();
            __syncthreads();
        }
        if (h == 0) {
            issue_raw(1);
            issue_A(1, 0, 0);
            cpa_commit();
            cpa_wait0();
            __syncthreads();
        }
    }

    // ---- epilogue ----
    const int g = lid >> 2, q = lid & 3;
    #pragma unroll
    for (int mt = 0; mt < 2; ++mt) {
        const int oc0 = wm * 32 + mt * 16 + g;
        const float bv0 = bias[oc0];
        const float bv1 = bias[oc0 + 8];
        #pragma unroll
        for (int nt = 0; nt < 7; ++nt) {
            const int col = wn * 56 + nt * 8 + 2 * q;
            float2 v0, v1;
            v0.x = acc[mt][nt][0] + bv0; v0.y = acc[mt][nt][1] + bv0;
            v1.x = acc[mt][nt][2] + bv1; v1.y = acc[mt][nt][3] + bv1;
            float* base = out + (((size_t)n * 128 + oc0) * 112 + oh) * 112 + col;
            *reinterpret_cast<float2*>(base) = v0;
            *reinterpret_cast<float2*>(base + 8 * 112 * 112) = v1;
        }
    }
}

extern "C" void kernel_launch(void* const* d_in, const int* in_sizes, int n_in,
                              void* d_out, int out_size)
{
    const float* x    = (const float*)d_in[0];
    const float* wgt  = (const float*)d_in[1];
    const float* bias = (const float*)d_in[2];
    float* out        = (float*)d_out;

    prep_all<<<3584 + 288, 256>>>(x, wgt);

    cudaFuncSetAttribute(conv3x3_fp16,
                         cudaFuncAttributeMaxDynamicSharedMemorySize, SMEM_BYTES);
    conv3x3_fp16<<<32 * 112, 256, SMEM_BYTES>>>(bias, out);
}

// round 13
// speedup vs baseline: 1.1129x; 1.1129x over previous
#include <cuda_runtime.h>
#include <cuda_fp16.h>
#include <cstdint>

// x[32,64,112,112] (*) w[128,64,3,3] + b[128] -> out[32,128,112,112], pad=1
// Conv as 9 shifted K=32 GEMM passes x 2 ic-halves. CTA = (n, oh): D[128 oc][112 px].
// 128 thr (4 warps, 2M x 2N), warp tile 64 oc x 56 px (mt=4, nt=7) -> 1.07 ldsm-wf/mma.
// fp16 mma m16n8k16 (f32 accum); 16B cp.async staging; 3 CTA/SM.

#define KTOT 576
#define STRB 80                           // smem row stride (bytes): conflict-free ldsm
#define RAW_BYTES  (342*STRB)             // 27360
#define ABUF_BYTES (128*STRB)             // 10240
#define SMEM_BYTES (RAW_BYTES + 2*ABUF_BYTES)   // 47840

__device__ __align__(16) __half Wt[2*9*128*32];              // re-laid weights
__device__ __align__(16) __half Xt[(size_t)32*112*112*64];   // NHWC input

__device__ __forceinline__ void ldsm4(uint32_t* r, uint32_t addr) {
    asm volatile("ldmatrix.sync.aligned.m8n8.x4.shared.b16 {%0,%1,%2,%3}, [%4];"
                 : "=r"(r[0]), "=r"(r[1]), "=r"(r[2]), "=r"(r[3]) : "r"(addr));
}
__device__ __forceinline__ void ldsm2(uint32_t* r, uint32_t addr) {
    asm volatile("ldmatrix.sync.aligned.m8n8.x2.shared.b16 {%0,%1}, [%2];"
                 : "=r"(r[0]), "=r"(r[1]) : "r"(addr));
}
__device__ __forceinline__ void mma16(float* d, const uint32_t* a, uint32_t b0, uint32_t b1) {
    asm volatile(
        "mma.sync.aligned.m16n8k16.row.col.f32.f16.f16.f32 "
        "{%0,%1,%2,%3}, {%4,%5,%6,%7}, {%8,%9}, {%0,%1,%2,%3};"
        : "+f"(d[0]), "+f"(d[1]), "+f"(d[2]), "+f"(d[3])
        : "r"(a[0]), "r"(a[1]), "r"(a[2]), "r"(a[3]), "r"(b0), "r"(b1));
}
__device__ __forceinline__ void cpa16(uint32_t dst, const void* src) {
    asm volatile("cp.async.ca.shared.global [%0], [%1], 16;" :: "r"(dst), "l"(src));
}
__device__ __forceinline__ void cpa16z(uint32_t dst, const void* src, uint32_t sz) {
    asm volatile("cp.async.ca.shared.global [%0], [%1], 16, %2;"
                 :: "r"(dst), "l"(src), "r"(sz));
}
__device__ __forceinline__ void cpa_commit() { asm volatile("cp.async.commit_group;"); }
__device__ __forceinline__ void cpa_wait0()  { asm volatile("cp.async.wait_group 0;" ::: "memory"); }

__global__ void prep_weights(const float* __restrict__ w) {
    const int i = blockIdx.x * 256 + threadIdx.x;     // 73728 total
    const int icl = i & 31;
    const int t   = i >> 5;
    const int oc  = t & 127;
    const int hr  = t >> 7;
    const int r   = hr % 9;
    const int h   = hr / 9;
    Wt[i] = __float2half_rn(w[oc * KTOT + (h * 32 + icl) * 9 + r]);
}

// x[n][c][h][w] -> Xt[n][h][w][c] fp16, vectorized. One (n,h) slice per block.
__global__ __launch_bounds__(256)
void prep_x(const float* __restrict__ x) {
    __shared__ float tile[64][116];                   // stride 116: aligned STS.128
    const int tid = threadIdx.x;
    const int n = blockIdx.x / 112, h = blockIdx.x - n * 112;
    const float* src = x + ((size_t)n * 64 * 112 + h) * 112;
    #pragma unroll
    for (int i = tid; i < 64 * 28; i += 256) {        // float4 reads, coalesced
        const int c = i / 28, w4 = i - c * 28;
        const float4 v = *reinterpret_cast<const float4*>(src + (size_t)c * 12544 + w4 * 4);
        *reinterpret_cast<float4*>(&tile[c][w4 * 4]) = v;
    }
    __syncthreads();
    __half2* dst = reinterpret_cast<__half2*>(Xt + ((size_t)(n * 112 + h) * 112) * 64);
    #pragma unroll
    for (int i = tid; i < 112 * 32; i += 256) {       // coalesced half2 writes
        const int wp = i >> 5, c2 = i & 31;
        dst[i] = __floats2half2_rn(tile[2 * c2][wp], tile[2 * c2 + 1][wp]);
    }
}

__global__ __launch_bounds__(128, 3)
void conv3x3_fp16w(const float* __restrict__ bias,
                   float* __restrict__ out)
{
    extern __shared__ uint32_t sm[];

    const int tid = threadIdx.x;
    const int lid = tid & 31;
    const int wid = tid >> 5;                    // 0..3
    const int wm  = wid & 1;                     // 64 oc per warp
    const int wn  = wid >> 1;                    // 56 px per warp

    const int bz = blockIdx.x;
    const int n  = bz / 112;
    const int oh = bz - n * 112;

    const uint32_t smem_b = (uint32_t)__cvta_generic_to_shared(sm);
    const uint32_t rawB = smem_b;                          // Raw [342 px][80B]
    const uint32_t AsmB = smem_b + RAW_BYTES;              // 2 x [128 oc][80B]

    const uint32_t aOff  = AsmB + (wm * 64 + (lid & 15)) * STRB + ((lid >> 4) << 4);
    const uint32_t bOff4 = (lid & 15) * STRB + ((lid >> 4) << 4);
    const uint32_t bOff2 = (lid & 7) * STRB + (((lid >> 3) & 1) << 4);

    float acc[4][7][4];
    #pragma unroll
    for (int mt = 0; mt < 4; ++mt)
        #pragma unroll
        for (int nt = 0; nt < 7; ++nt)
            #pragma unroll
            for (int e = 0; e < 4; ++e) acc[mt][nt][e] = 0.0f;

    // ---- A pass tile: 4x 16B cp.async from Wt (128 rows x 64B) ----
    auto issue_A = [&](int h, int r, int buf) {
        const __half* src = Wt + (h * 9 + r) * 4096;       // [128][32] halves
        const int q = tid & 3, ocr = tid >> 2;             // 32 rows per iter
        const uint32_t dbase = AsmB + buf * ABUF_BYTES;
        #pragma unroll
        for (int it = 0; it < 4; ++it) {
            const int oc = it * 32 + ocr;
            cpa16(dbase + oc * STRB + q * 16, src + oc * 32 + q * 8);
        }
    };

    // ---- raw tile for ic-half h: one 16B cp.async per (pixel, 8-ic chunk) ----
    auto issue_raw = [&](int hlf) {
        const __half* xb = Xt + (size_t)n * 12544 * 64 + hlf * 32;
        const int q = tid & 3;
        #pragma unroll 1
        for (int p = tid >> 2; p < 342; p += 32) {
            const int row = p / 114, col = p - row * 114;
            const int ih = oh - 1 + row;
            const int iw = col - 1;
            const bool ok = (ih >= 0) & (ih < 112) & (iw >= 0) & (iw < 112);
            const __half* src = ok ? xb + ((size_t)ih * 112 + iw) * 64 + q * 8 : Xt;
            cpa16z(rawB + p * STRB + q * 16, src, ok ? 16u : 0u);
        }
    };

    // ---- one (kh,kw) GEMM pass, K=32 (2 k16 mma steps), warp tile 64x56 ----
    auto compute = [&](int r, int buf) {
        const int kh = r / 3, kw = r - 3 * kh;
        const uint32_t b4 = rawB + (kh * 114 + kw + wn * 56) * STRB + bOff4;
        const uint32_t b2 = rawB + (kh * 114 + kw + wn * 56 + 48) * STRB + bOff2;
        const uint32_t aB = aOff + buf * ABUF_BYTES;
        #pragma unroll
        for (int s = 0; s < 2; ++s) {
            uint32_t a[4][4];
            #pragma unroll
            for (int mt = 0; mt < 4; ++mt)
                ldsm4(a[mt], aB + mt * (16 * STRB) + s * 32);
            #pragma unroll
            for (int np = 0; np < 3; ++np) {
                uint32_t bf[4];
                ldsm4(bf, b4 + np * (16 * STRB) + s * 32);
                #pragma unroll
                for (int half = 0; half < 2; ++half) {
                    const int nt = np * 2 + half;
                    #pragma unroll
                    for (int mt = 0; mt < 4; ++mt)
                        mma16(acc[mt][nt], a[mt], bf[half], bf[2 + half]);
                }
            }
            uint32_t bg[2];
            ldsm2(bg, b2 + s * 32);
            #pragma unroll
            for (int mt = 0; mt < 4; ++mt)
                mma16(acc[mt][6], a[mt], bg[0], bg[1]);
        }
    };

    // ---- pipelined main loop ----
    issue_raw(0);
    issue_A(0, 0, 0);
    cpa_commit();
    cpa_wait0();
    __syncthreads();

    #pragma unroll 1
    for (int h = 0; h < 2; ++h) {
        #pragma unroll 1
        for (int r = 0; r < 9; ++r) {
            if (r < 8) { issue_A(h, r + 1, (r + 1) & 1); cpa_commit(); }
            compute(r, r & 1);
            if (r < 8) cpa_wait0();
            __syncthreads();
        }
        if (h == 0) {
            issue_raw(1);
            issue_A(1, 0, 0);
            cpa_commit();
            cpa_wait0();
            __syncthreads();
        }
    }

    // ---- epilogue ----
    const int g = lid >> 2, q = lid & 3;
    #pragma unroll
    for (int mt = 0; mt < 4; ++mt) {
        const int oc0 = wm * 64 + mt * 16 + g;
        const float bv0 = bias[oc0];
        const float bv1 = bias[oc0 + 8];
        #pragma unroll
        for (int nt = 0; nt < 7; ++nt) {
            const int col = wn * 56 + nt * 8 + 2 * q;
            float2 v0, v1;
            v0.x = acc[mt][nt][0] + bv0; v0.y = acc[mt][nt][1] + bv0;
            v1.x = acc[mt][nt][2] + bv1; v1.y = acc[mt][nt][3] + bv1;
            float* base = out + (((size_t)n * 128 + oc0) * 112 + oh) * 112 + col;
            *reinterpret_cast<float2*>(base) = v0;
            *reinterpret_cast<float2*>(base + 8 * 112 * 112) = v1;
        }
    }
}

extern "C" void kernel_launch(void* const* d_in, const int* in_sizes, int n_in,
                              void* d_out, int out_size)
{
    const float* x    = (const float*)d_in[0];
    const float* wgt  = (const float*)d_in[1];
    const float* bias = (const float*)d_in[2];
    float* out        = (float*)d_out;

    prep_weights<<<288, 256>>>(wgt);
    prep_x<<<32 * 112, 256>>>(x);

    cudaFuncSetAttribute(conv3x3_fp16w,
                         cudaFuncAttributeMaxDynamicSharedMemorySize, SMEM_BYTES);
    conv3x3_fp16w<<<32 * 112, 128, SMEM_BYTES>>>(bias, out);
}